// round 15
// baseline (speedup 1.0000x reference)
#include <cuda_runtime.h>
#include <math.h>

#define BB 32
#define CC 256
#define HH 96
#define WW 96
#define CR 64
#define PITCH 96
#define POOLN (BB*CC)         // 8192 pool blocks
#define PROJB (5*BB)          // 160 proj blocks

// Scratch (no allocs allowed)
__device__ float g_pooled[BB*9*CC];     // [b][p][c] block sums
__device__ float g_weight[BB*9*CC];     // [b][p][c]
__device__ float g_bias[BB*CC];
__device__ float g_w1t[CC*CR];          // [k][o], BN inv folded
__device__ float g_w2t[CR*2*CC];        // [k][n]
__device__ float g_bnb[CR];
__device__ float g_dwt[2*9*CC];         // [g][p][c]
__device__ unsigned g_cnt[BB];          // pool contributions (256/sample/launch, never reset)
__device__ unsigned g_prep;             // prep contributions (114/launch, never reset)
__device__ unsigned g_pepoch;           // proj arrivals (160/launch, never reset)

// ---------------------------------------------------------------------------
// Kernel 1: pool (bids 0..8191, wait-free) + proj (bids 8192..8351, spin on
// their sample's 256 pool contributions; scheduled last). R13 version.
// ---------------------------------------------------------------------------
__global__ __launch_bounds__(288, 7) void pool_proj_kernel(
    const float* __restrict__ x,
    const float* __restrict__ dyn_weight,
    const float* __restrict__ dyn_bias,
    const float* __restrict__ w1,
    const float* __restrict__ bn_gamma,
    const float* __restrict__ bn_beta,
    const float* __restrict__ bn_mean,
    const float* __restrict__ bn_var,
    const float* __restrict__ w2,
    const float* __restrict__ b2)
{
    __shared__ float scr[1216];
    __shared__ unsigned s_u;
    int bid = blockIdx.x;
    int t = threadIdx.x;

    if (bid < POOLN) {
        if (bid < 114) {
            int idx = bid * 288 + t;
            if (idx < CC*CR) {
                int k = idx >> 6, o = idx & 63;
                float inv = bn_gamma[o] * rsqrtf(bn_var[o] + 1e-5f);
                g_w1t[idx] = w1[o * CC + k] * inv;
            }
            if (idx < CR*2*CC) {
                int k = idx >> 9, n = idx & 511;
                g_w2t[idx] = w2[n * CR + k];
            }
            if (idx < 2*9*CC) {
                int g = idx / (9*CC);
                int rem = idx - g * 9 * CC;
                int p = rem >> 8, c2 = rem & 255;
                g_dwt[idx] = dyn_weight[(g * CC + c2) * 9 + p];
            }
            if (idx < CR) {
                float inv = bn_gamma[idx] * rsqrtf(bn_var[idx] + 1e-5f);
                g_bnb[idx] = bn_beta[idx] - bn_mean[idx] * inv;
            }
            __threadfence();
            __syncthreads();
            if (t == 0) atomicAdd(&g_prep, 1u);
        }

        int bc = bid;
        int b = bc >> 8, c = bc & 255;
        int w = t >> 5, lane = t & 31;
        int cy = w / 3, cx = w % 3;
        const float* base = x + (size_t)bc * (HH*WW) + cy * 32 * WW + cx * 32;
        float s = 0.f;
#pragma unroll
        for (int i = 0; i < 8; i++) {
            int f = lane + i * 32;
            int row = f >> 3, c4 = f & 7;
            float4 v = __ldcs(reinterpret_cast<const float4*>(base + row * WW + c4 * 4));
            s += v.x + v.y + v.z + v.w;
        }
#pragma unroll
        for (int o = 16; o; o >>= 1) s += __shfl_xor_sync(0xffffffffu, s, o);
        if (lane == 0) g_pooled[(b * 9 + w) * CC + c] = s;
        __threadfence();
        __syncthreads();
        if (t == 0) atomicAdd(&g_cnt[b], 1u);
        return;
    }

    int pid = bid - POOLN;
    int b = pid / 5, pq = pid % 5;

    if (t == 0) {
        unsigned R = atomicAdd(&g_pepoch, 1u) / PROJB;
        while (atomicAdd(&g_prep, 0u) < 114u * (R + 1u)) __nanosleep(128);
        while (atomicAdd(&g_cnt[b], 0u) < 256u * (R + 1u)) __nanosleep(128);
        s_u = 1u;
    }
    __syncthreads();
    __threadfence();

    float* sv0 = scr;
    float* sv1 = scr + 256;
    float* pa  = scr + 512;
    float* sh0 = scr + 1024;
    float* sh1 = scr + 1088;
    int p = pq, p2 = pq + 5;

    if (t < CC) {
        float v0 = g_pooled[(b * 9 + p) * CC + t] * (1.0f / 1024.0f);
        float v1;
        if (p2 < 9) {
            v1 = g_pooled[(b * 9 + p2) * CC + t] * (1.0f / 1024.0f);
        } else {
            float s = 0.f;
#pragma unroll
            for (int q = 0; q < 9; q++) s += g_pooled[(b * 9 + q) * CC + t];
            v1 = s * (1.0f / (HH * WW));
        }
        sv0[t] = v0; sv1[t] = v1;
    }
    __syncthreads();

    if (t < 256) {
        int o = t & 63, slice = t >> 6;
        const float* w1s = g_w1t + slice * 64 * CR + o;
        const float* a0p = sv0 + slice * 64;
        const float* a1p = sv1 + slice * 64;
        float acc0 = 0.f, acc1 = 0.f;
#pragma unroll 8
        for (int k = 0; k < 64; k++) {
            float w = w1s[k * CR];
            acc0 = fmaf(w, a0p[k], acc0);
            acc1 = fmaf(w, a1p[k], acc1);
        }
        pa[t] = acc0; pa[256 + t] = acc1;
    }
    __syncthreads();

    if (t < 128) {
        int pos = t >> 6, oo = t & 63;
        const float* pp = pa + pos * 256;
        float h = pp[oo] + pp[oo + 64] + pp[oo + 128] + pp[oo + 192] + g_bnb[oo];
        h = 0.5f * h * (1.0f + erff(h * 0.70710678118654752f));
        if (pos) sh1[oo] = h; else sh0[oo] = h;
    }
    __syncthreads();

    if (t < CC) {
        int c = t;
        float a0 = b2[c], a1 = b2[CC + c];
        float d0 = a0, d1 = a1;
#pragma unroll 8
        for (int k = 0; k < CR; k++) {
            float w_0 = g_w2t[k * 512 + c];
            float w_1 = g_w2t[k * 512 + CC + c];
            float h0 = sh0[k], h1 = sh1[k];
            a0 = fmaf(w_0, h0, a0); a1 = fmaf(w_1, h0, a1);
            d0 = fmaf(w_0, h1, d0); d1 = fmaf(w_1, h1, d1);
        }
        {
            float m = fmaxf(a0, a1);
            float e0 = __expf(a0 - m), e1 = __expf(a1 - m);
            float r = 1.0f / (e0 + e1);
            g_weight[(b * 9 + p) * CC + c] = e0 * r * g_dwt[p * CC + c]
                                           + e1 * r * g_dwt[(9 + p) * CC + c];
        }
        {
            float m = fmaxf(d0, d1);
            float e0 = __expf(d0 - m), e1 = __expf(d1 - m);
            float r = 1.0f / (e0 + e1);
            if (p2 < 9) {
                g_weight[(b * 9 + p2) * CC + c] = e0 * r * g_dwt[p2 * CC + c]
                                                + e1 * r * g_dwt[(9 + p2) * CC + c];
            } else {
                g_bias[b * CC + c] = e0 * r * dyn_bias[c] + e1 * r * dyn_bias[CC + c];
            }
        }
    }
}

// ---------------------------------------------------------------------------
// Kernel 2: depthwise 3x3 conv + bias, HALF-IMAGE tiles.
// 16384 blocks; block handles 48 output rows of one (b,c). Tile = 50 rows x
// 96 pitch = 18.75KB -> 7 blocks/SM (63/64 warps). Thread = 4 cols x 4 rows.
// ---------------------------------------------------------------------------
__global__ __launch_bounds__(288, 7) void dwconv_kernel(const float* __restrict__ x,
                                                        float* __restrict__ y) {
    __shared__ float tile[50 * PITCH];    // 18.75 KB
    int bid = blockIdx.x;
    int bc = bid >> 1;
    int h = bid & 1;
    int gy0 = h * 48;                     // first output row of this half
    int t = threadIdx.x;
    const float* img = x + (size_t)bc * (HH*WW);
    float* outimg = y + (size_t)bc * (HH*WW);

    // stage rows gy0-1 .. gy0+48 into smem rows 0..49 (OOB rows zeroed)
    float4 z4 = make_float4(0.f,0.f,0.f,0.f);
#pragma unroll
    for (int i = 0; i < 5; i++) {
        int idx = t + i * 288;            // 0..1439, need 0..1199
        if (idx < 1200) {
            int sr = idx / 24, j = idx % 24;
            int gr = gy0 - 1 + sr;
            if (gr >= 0 && gr < HH) {
                unsigned sa = (unsigned)__cvta_generic_to_shared(&tile[sr * PITCH + j * 4]);
                asm volatile("cp.async.cg.shared.global [%0], [%1], 16;\n"
                             :: "r"(sa), "l"(img + gr * WW + j * 4));
            } else {
                *reinterpret_cast<float4*>(&tile[sr * PITCH + j * 4]) = z4;
            }
        }
    }
    asm volatile("cp.async.commit_group;\n");
    asm volatile("cp.async.wait_group 0;\n");
    __syncthreads();

    int b = bc >> 8, c = bc & 255;
    float w0 = g_weight[(b*9+0)*CC+c], w1_ = g_weight[(b*9+1)*CC+c], w2_ = g_weight[(b*9+2)*CC+c];
    float w3 = g_weight[(b*9+3)*CC+c], w4  = g_weight[(b*9+4)*CC+c], w5  = g_weight[(b*9+5)*CC+c];
    float w6 = g_weight[(b*9+6)*CC+c], w7  = g_weight[(b*9+7)*CC+c], w8  = g_weight[(b*9+8)*CC+c];
    float bv = g_bias[bc];

    int tx = t % 24;                      // col group: cols 4tx..4tx+3
    int ry = t / 24;                      // row group 0..11: output rows gy0+4ry..+3
    int x0 = tx * 4;
    int lr0 = ry * 4;                     // first smem row for this thread
    bool hasL = (tx > 0), hasR = (tx < 23);

    float4 aA = make_float4(0.f,0.f,0.f,0.f);
    float4 aB = make_float4(0.f,0.f,0.f,0.f);
    float4 aC = make_float4(0.f,0.f,0.f,0.f);

#pragma unroll
    for (int s = 0; s < 6; ++s) {
        const float* row = &tile[(lr0 + s) * PITCH + x0];
        float4 v = *reinterpret_cast<const float4*>(row);
        float l  = hasL ? row[-1] : 0.f;
        float rr = hasR ? row[4]  : 0.f;
        float c0 = v.x, c1 = v.y, c2 = v.z, c3 = v.w;

        aA.x = fmaf(l,  w6, fmaf(c0, w7, fmaf(c1, w8, aA.x)));
        aA.y = fmaf(c0, w6, fmaf(c1, w7, fmaf(c2, w8, aA.y)));
        aA.z = fmaf(c1, w6, fmaf(c2, w7, fmaf(c3, w8, aA.z)));
        aA.w = fmaf(c2, w6, fmaf(c3, w7, fmaf(rr, w8, aA.w)));

        aB.x = fmaf(l,  w3, fmaf(c0, w4, fmaf(c1, w5, aB.x)));
        aB.y = fmaf(c0, w3, fmaf(c1, w4, fmaf(c2, w5, aB.y)));
        aB.z = fmaf(c1, w3, fmaf(c2, w4, fmaf(c3, w5, aB.z)));
        aB.w = fmaf(c2, w3, fmaf(c3, w4, fmaf(rr, w5, aB.w)));

        aC.x = fmaf(l,  w0, fmaf(c0, w1_, fmaf(c1, w2_, aC.x)));
        aC.y = fmaf(c0, w0, fmaf(c1, w1_, fmaf(c2, w2_, aC.y)));
        aC.z = fmaf(c1, w0, fmaf(c2, w1_, fmaf(c3, w2_, aC.z)));
        aC.w = fmaf(c2, w0, fmaf(c3, w1_, fmaf(rr, w2_, aC.w)));

        if (s >= 2) {
            int yo = gy0 + lr0 + s - 2;
            float4 o;
            o.x = aA.x + bv; o.y = aA.y + bv; o.z = aA.z + bv; o.w = aA.w + bv;
            __stcs(reinterpret_cast<float4*>(outimg + yo * WW + x0), o);
        }
        aA = aB; aB = aC;
        aC = make_float4(0.f,0.f,0.f,0.f);
    }
}

extern "C" void kernel_launch(void* const* d_in, const int* in_sizes, int n_in,
                              void* d_out, int out_size) {
    const float* x          = (const float*)d_in[0];
    const float* dyn_weight = (const float*)d_in[1];
    const float* dyn_bias   = (const float*)d_in[2];
    const float* w1         = (const float*)d_in[3];
    const float* bn_gamma   = (const float*)d_in[4];
    const float* bn_beta    = (const float*)d_in[5];
    const float* bn_mean    = (const float*)d_in[6];
    const float* bn_var     = (const float*)d_in[7];
    const float* w2         = (const float*)d_in[8];
    const float* b2         = (const float*)d_in[9];
    float* out = (float*)d_out;

    pool_proj_kernel<<<POOLN + PROJB, 288>>>(x, dyn_weight, dyn_bias, w1,
                                             bn_gamma, bn_beta, bn_mean, bn_var,
                                             w2, b2);
    dwconv_kernel<<<2 * POOLN, 288>>>(x, out);
}

// round 16
// speedup vs baseline: 1.1530x; 1.1530x over previous
#include <cuda_runtime.h>
#include <math.h>

#define BB 32
#define CC 256
#define HH 96
#define WW 96
#define CR 64
#define PITCH 96
#define POOLN (BB*CC)         // 8192 pool blocks
#define PROJB (5*BB)          // 160 proj blocks

// Scratch (no allocs allowed)
__device__ float g_pooled[BB*9*CC];     // [b][p][c] block sums
__device__ float g_weight[BB*9*CC];     // [b][p][c]
__device__ float g_bias[BB*CC];
__device__ float g_w1t[CC*CR];          // [k][o], BN inv folded
__device__ float g_w2t[CR*2*CC];        // [k][n]
__device__ float g_bnb[CR];
__device__ float g_dwt[2*9*CC];         // [g][p][c]
__device__ unsigned g_cnt[BB];          // pool contributions (256/sample/launch, never reset)
__device__ unsigned g_prep;             // prep contributions (114/launch, never reset)
__device__ unsigned g_pepoch;           // proj arrivals (160/launch, never reset)

// ---------------------------------------------------------------------------
// Kernel 1 (PDL primary): pool (bids 0..8191, wait-free) + proj (bids
// 8192..8351, spin on their sample's 256 pool contributions). R13 logic;
// every block triggers programmatic launch completion at entry so dwconv
// blocks can fill SMs as pool waves retire.
// ---------------------------------------------------------------------------
__global__ __launch_bounds__(288, 7) void pool_proj_kernel(
    const float* __restrict__ x,
    const float* __restrict__ dyn_weight,
    const float* __restrict__ dyn_bias,
    const float* __restrict__ w1,
    const float* __restrict__ bn_gamma,
    const float* __restrict__ bn_beta,
    const float* __restrict__ bn_mean,
    const float* __restrict__ bn_var,
    const float* __restrict__ w2,
    const float* __restrict__ b2)
{
    __shared__ float scr[1216];
    __shared__ unsigned s_u;
    int bid = blockIdx.x;
    int t = threadIdx.x;

    cudaTriggerProgrammaticLaunchCompletion();

    if (bid < POOLN) {
        if (bid < 114) {
            int idx = bid * 288 + t;
            if (idx < CC*CR) {
                int k = idx >> 6, o = idx & 63;
                float inv = bn_gamma[o] * rsqrtf(bn_var[o] + 1e-5f);
                g_w1t[idx] = w1[o * CC + k] * inv;
            }
            if (idx < CR*2*CC) {
                int k = idx >> 9, n = idx & 511;
                g_w2t[idx] = w2[n * CR + k];
            }
            if (idx < 2*9*CC) {
                int g = idx / (9*CC);
                int rem = idx - g * 9 * CC;
                int p = rem >> 8, c2 = rem & 255;
                g_dwt[idx] = dyn_weight[(g * CC + c2) * 9 + p];
            }
            if (idx < CR) {
                float inv = bn_gamma[idx] * rsqrtf(bn_var[idx] + 1e-5f);
                g_bnb[idx] = bn_beta[idx] - bn_mean[idx] * inv;
            }
            __threadfence();
            __syncthreads();
            if (t == 0) atomicAdd(&g_prep, 1u);
        }

        int bc = bid;
        int b = bc >> 8, c = bc & 255;
        int w = t >> 5, lane = t & 31;
        int cy = w / 3, cx = w % 3;
        const float* base = x + (size_t)bc * (HH*WW) + cy * 32 * WW + cx * 32;
        float s = 0.f;
#pragma unroll
        for (int i = 0; i < 8; i++) {
            int f = lane + i * 32;
            int row = f >> 3, c4 = f & 7;
            float4 v = __ldcs(reinterpret_cast<const float4*>(base + row * WW + c4 * 4));
            s += v.x + v.y + v.z + v.w;
        }
#pragma unroll
        for (int o = 16; o; o >>= 1) s += __shfl_xor_sync(0xffffffffu, s, o);
        if (lane == 0) g_pooled[(b * 9 + w) * CC + c] = s;
        __threadfence();
        __syncthreads();
        if (t == 0) atomicAdd(&g_cnt[b], 1u);
        return;
    }

    int pid = bid - POOLN;
    int b = pid / 5, pq = pid % 5;

    if (t == 0) {
        unsigned R = atomicAdd(&g_pepoch, 1u) / PROJB;
        while (atomicAdd(&g_prep, 0u) < 114u * (R + 1u)) __nanosleep(128);
        while (atomicAdd(&g_cnt[b], 0u) < 256u * (R + 1u)) __nanosleep(128);
        s_u = 1u;
    }
    __syncthreads();
    __threadfence();

    float* sv0 = scr;
    float* sv1 = scr + 256;
    float* pa  = scr + 512;
    float* sh0 = scr + 1024;
    float* sh1 = scr + 1088;
    int p = pq, p2 = pq + 5;

    if (t < CC) {
        float v0 = g_pooled[(b * 9 + p) * CC + t] * (1.0f / 1024.0f);
        float v1;
        if (p2 < 9) {
            v1 = g_pooled[(b * 9 + p2) * CC + t] * (1.0f / 1024.0f);
        } else {
            float s = 0.f;
#pragma unroll
            for (int q = 0; q < 9; q++) s += g_pooled[(b * 9 + q) * CC + t];
            v1 = s * (1.0f / (HH * WW));
        }
        sv0[t] = v0; sv1[t] = v1;
    }
    __syncthreads();

    if (t < 256) {
        int o = t & 63, slice = t >> 6;
        const float* w1s = g_w1t + slice * 64 * CR + o;
        const float* a0p = sv0 + slice * 64;
        const float* a1p = sv1 + slice * 64;
        float acc0 = 0.f, acc1 = 0.f;
#pragma unroll 8
        for (int k = 0; k < 64; k++) {
            float w = w1s[k * CR];
            acc0 = fmaf(w, a0p[k], acc0);
            acc1 = fmaf(w, a1p[k], acc1);
        }
        pa[t] = acc0; pa[256 + t] = acc1;
    }
    __syncthreads();

    if (t < 128) {
        int pos = t >> 6, oo = t & 63;
        const float* pp = pa + pos * 256;
        float h = pp[oo] + pp[oo + 64] + pp[oo + 128] + pp[oo + 192] + g_bnb[oo];
        h = 0.5f * h * (1.0f + erff(h * 0.70710678118654752f));
        if (pos) sh1[oo] = h; else sh0[oo] = h;
    }
    __syncthreads();

    if (t < CC) {
        int c = t;
        float a0 = b2[c], a1 = b2[CC + c];
        float d0 = a0, d1 = a1;
#pragma unroll 8
        for (int k = 0; k < CR; k++) {
            float w_0 = g_w2t[k * 512 + c];
            float w_1 = g_w2t[k * 512 + CC + c];
            float h0 = sh0[k], h1 = sh1[k];
            a0 = fmaf(w_0, h0, a0); a1 = fmaf(w_1, h0, a1);
            d0 = fmaf(w_0, h1, d0); d1 = fmaf(w_1, h1, d1);
        }
        {
            float m = fmaxf(a0, a1);
            float e0 = __expf(a0 - m), e1 = __expf(a1 - m);
            float r = 1.0f / (e0 + e1);
            g_weight[(b * 9 + p) * CC + c] = e0 * r * g_dwt[p * CC + c]
                                           + e1 * r * g_dwt[(9 + p) * CC + c];
        }
        {
            float m = fmaxf(d0, d1);
            float e0 = __expf(d0 - m), e1 = __expf(d1 - m);
            float r = 1.0f / (e0 + e1);
            if (p2 < 9) {
                g_weight[(b * 9 + p2) * CC + c] = e0 * r * g_dwt[p2 * CC + c]
                                                + e1 * r * g_dwt[(9 + p2) * CC + c];
            } else {
                g_bias[b * CC + c] = e0 * r * dyn_bias[c] + e1 * r * dyn_bias[CC + c];
            }
        }
    }
}

// ---------------------------------------------------------------------------
// Kernel 2 (PDL secondary): depthwise 3x3 conv + bias. Stages x (independent
// of primary results) BEFORE cudaGridDependencySynchronize(); weights read
// after. Compute identical to R8/R13 (proven 94.8us @ 72% DRAM).
// ---------------------------------------------------------------------------
__global__ __launch_bounds__(288, 6) void dwconv_kernel(const float* __restrict__ x,
                                                        float* __restrict__ y) {
    __shared__ float tile[98 * PITCH];
    int bc = blockIdx.x;
    int t = threadIdx.x;
    const float* img = x + (size_t)bc * (HH*WW);
    float* outimg = y + (size_t)bc * (HH*WW);

    float4 z4 = make_float4(0.f,0.f,0.f,0.f);
    if (t < 24) {
        *reinterpret_cast<float4*>(&tile[t * 4]) = z4;
    } else if (t < 48) {
        *reinterpret_cast<float4*>(&tile[97 * PITCH + (t - 24) * 4]) = z4;
    }

    // stage x (independent of primary's outputs) — overlaps primary's tail
#pragma unroll
    for (int i = 0; i < 8; i++) {
        int idx = t + i * 288;
        int r = idx / 24, j = idx % 24;
        unsigned sa = (unsigned)__cvta_generic_to_shared(&tile[(r + 1) * PITCH + j * 4]);
        asm volatile("cp.async.cg.shared.global [%0], [%1], 16;\n"
                     :: "r"(sa), "l"(img + r * WW + j * 4));
    }
    asm volatile("cp.async.commit_group;\n");

    // wait for the full primary grid (pool + proj) before touching weights
    cudaGridDependencySynchronize();

    int b = bc >> 8, c = bc & 255;
    float w0 = g_weight[(b*9+0)*CC+c], w1_ = g_weight[(b*9+1)*CC+c], w2_ = g_weight[(b*9+2)*CC+c];
    float w3 = g_weight[(b*9+3)*CC+c], w4  = g_weight[(b*9+4)*CC+c], w5  = g_weight[(b*9+5)*CC+c];
    float w6 = g_weight[(b*9+6)*CC+c], w7  = g_weight[(b*9+7)*CC+c], w8  = g_weight[(b*9+8)*CC+c];
    float bv = g_bias[bc];

    asm volatile("cp.async.wait_group 0;\n");
    __syncthreads();

    int tx = t % 24;
    int ty = t / 24;
    int x0 = tx * 4;
    int r0 = ty * 8;
    bool hasL = (tx > 0), hasR = (tx < 23);

    float4 aA = make_float4(0.f,0.f,0.f,0.f);
    float4 aB = make_float4(0.f,0.f,0.f,0.f);
    float4 aC = make_float4(0.f,0.f,0.f,0.f);

#pragma unroll
    for (int s = 0; s < 10; ++s) {
        const float* row = &tile[(r0 + s) * PITCH + x0];
        float4 v = *reinterpret_cast<const float4*>(row);
        float l  = hasL ? row[-1] : 0.f;
        float rr = hasR ? row[4]  : 0.f;
        float c0 = v.x, c1 = v.y, c2 = v.z, c3 = v.w;

        aA.x = fmaf(l,  w6, fmaf(c0, w7, fmaf(c1, w8, aA.x)));
        aA.y = fmaf(c0, w6, fmaf(c1, w7, fmaf(c2, w8, aA.y)));
        aA.z = fmaf(c1, w6, fmaf(c2, w7, fmaf(c3, w8, aA.z)));
        aA.w = fmaf(c2, w6, fmaf(c3, w7, fmaf(rr, w8, aA.w)));

        aB.x = fmaf(l,  w3, fmaf(c0, w4, fmaf(c1, w5, aB.x)));
        aB.y = fmaf(c0, w3, fmaf(c1, w4, fmaf(c2, w5, aB.y)));
        aB.z = fmaf(c1, w3, fmaf(c2, w4, fmaf(c3, w5, aB.z)));
        aB.w = fmaf(c2, w3, fmaf(c3, w4, fmaf(rr, w5, aB.w)));

        aC.x = fmaf(l,  w0, fmaf(c0, w1_, fmaf(c1, w2_, aC.x)));
        aC.y = fmaf(c0, w0, fmaf(c1, w1_, fmaf(c2, w2_, aC.y)));
        aC.z = fmaf(c1, w0, fmaf(c2, w1_, fmaf(c3, w2_, aC.z)));
        aC.w = fmaf(c2, w0, fmaf(c3, w1_, fmaf(rr, w2_, aC.w)));

        if (s >= 2) {
            int yo = r0 + s - 2;
            float4 o;
            o.x = aA.x + bv; o.y = aA.y + bv; o.z = aA.z + bv; o.w = aA.w + bv;
            __stcs(reinterpret_cast<float4*>(outimg + yo * WW + x0), o);
        }
        aA = aB; aB = aC;
        aC = make_float4(0.f,0.f,0.f,0.f);
    }
}

extern "C" void kernel_launch(void* const* d_in, const int* in_sizes, int n_in,
                              void* d_out, int out_size) {
    const float* x          = (const float*)d_in[0];
    const float* dyn_weight = (const float*)d_in[1];
    const float* dyn_bias   = (const float*)d_in[2];
    const float* w1         = (const float*)d_in[3];
    const float* bn_gamma   = (const float*)d_in[4];
    const float* bn_beta    = (const float*)d_in[5];
    const float* bn_mean    = (const float*)d_in[6];
    const float* bn_var     = (const float*)d_in[7];
    const float* w2         = (const float*)d_in[8];
    const float* b2         = (const float*)d_in[9];
    float* out = (float*)d_out;

    pool_proj_kernel<<<POOLN + PROJB, 288>>>(x, dyn_weight, dyn_bias, w1,
                                             bn_gamma, bn_beta, bn_mean, bn_var,
                                             w2, b2);

    // PDL secondary: may begin launching as primary blocks trigger/retire;
    // correctness gated by cudaGridDependencySynchronize() inside the kernel.
    cudaLaunchConfig_t cfg = {};
    cfg.gridDim = dim3(POOLN);
    cfg.blockDim = dim3(288);
    cfg.dynamicSmemBytes = 0;
    cfg.stream = 0;
    cudaLaunchAttribute attr[1];
    attr[0].id = cudaLaunchAttributeProgrammaticStreamSerialization;
    attr[0].val.programmaticStreamSerializationAllowed = 1;
    cfg.attrs = attr;
    cfg.numAttrs = 1;
    cudaLaunchKernelEx(&cfg, dwconv_kernel, x, out);
}